// round 12
// baseline (speedup 1.0000x reference)
#include <cuda_runtime.h>
#include <cstdint>
#include <math.h>

#define LSTMN 256
#define CLSZ  8
#define EPC   32          // elements per CTA
#define GR    128         // gate rows per CTA (4 * EPC)
#define NTH   256
#define NBLK  6

struct __align__(16) Smem {
    float whh[GR * 256];      // 128 KB: own gate rows of w_hh
    float w1r[EPC * 256];     // 32 KB: w1 ROWS [rank*32, rank*32+32)
    float w2r[EPC * 256];     // 32 KB: w2 ROWS
    float candh[2][5][256];   // candidate h planes, double-buffered by parity
    float hanc[256];          // private anchor-h / enc0 staging
    float gxc[6][GR];         // gx cache: 0=enc0, 1=zero, 2..5=anchors
    float gtmp[GR];           // whh @ h
    float bsum[GR];
    float candc[5][EPC];      // candidate c (local)
    float c32[EPC], w2h32[EPC], v32[EPC];
    float aw1l[6][EPC];       // local rows of anchors_w1
    float red2[2][6 * CLSZ];  // logit partials, double-buffered
    float gum[8];
    float lp, ent;
    int   idx;
    unsigned long long mbar;
};

__device__ float g_lp[NBLK];
__device__ float g_ent[NBLK];
__device__ int   g_count;

// ---------------- low-level helpers ----------------

__device__ __forceinline__ uint32_t sm_u32(const void* p) {
    return (uint32_t)__cvta_generic_to_shared(p);
}
__device__ __forceinline__ uint32_t ctarank() {
    uint32_t r; asm("mov.u32 %0, %%cluster_ctarank;" : "=r"(r)); return r;
}
__device__ __forceinline__ void ds_st(uint32_t laddr, uint32_t rank, float val) {
    uint32_t ra;
    asm volatile("mapa.shared::cluster.u32 %0, %1, %2;" : "=r"(ra) : "r"(laddr), "r"(rank));
    asm volatile("st.shared::cluster.f32 [%0], %1;" :: "r"(ra), "f"(val) : "memory");
}
__device__ __forceinline__ void round_arrive(Smem* s, int tid) {
    asm volatile("fence.acq_rel.cluster;" ::: "memory");
    __syncthreads();
    if (tid == 0) {
        uint32_t la = sm_u32(&s->mbar);
#pragma unroll
        for (int r = 0; r < CLSZ; r++) {
            uint32_t ra;
            asm volatile("mapa.shared::cluster.u32 %0, %1, %2;"
                         : "=r"(ra) : "r"(la), "r"(r));
            asm volatile("mbarrier.arrive.shared::cluster.b64 _, [%0];"
                         :: "r"(ra) : "memory");
        }
    }
}
__device__ __forceinline__ void round_wait(Smem* s, int k) {
    uint32_t la = sm_u32(&s->mbar);
    uint32_t par = (uint32_t)(k & 1);
    uint32_t done;
    asm volatile(
        "{\n\t.reg .pred p;\n\t"
        "mbarrier.try_wait.parity.acquire.cluster.shared::cta.b64 p, [%1], %2;\n\t"
        "selp.b32 %0, 1, 0, p;\n\t}"
        : "=r"(done) : "r"(la), "r"(par) : "memory");
    if (!done) {
        asm volatile(
            "{\n\t.reg .pred P1;\n\t"
            "W%=:\n\t"
            "mbarrier.try_wait.parity.acquire.cluster.shared::cta.b64 P1, [%0], %1, 0x989680;\n\t"
            "@P1 bra D%=;\n\t"
            "bra W%=;\n\t"
            "D%=:\n\t}"
            :: "r"(la), "r"(par) : "memory");
    }
}

// threefry2x32, 20 rounds — exact JAX semantics
__device__ __forceinline__ uint2 tf2x32(uint2 key, uint2 ctr) {
    uint32_t ks0 = key.x, ks1 = key.y, ks2 = ks0 ^ ks1 ^ 0x1BD11BDAu;
    uint32_t x0 = ctr.x + ks0, x1 = ctr.y + ks1;
#define TF_RND(r) { x0 += x1; x1 = (x1 << (r)) | (x1 >> (32 - (r))); x1 ^= x0; }
    TF_RND(13) TF_RND(15) TF_RND(26) TF_RND(6)  x0 += ks1; x1 += ks2 + 1u;
    TF_RND(17) TF_RND(29) TF_RND(16) TF_RND(24) x0 += ks2; x1 += ks0 + 2u;
    TF_RND(13) TF_RND(15) TF_RND(26) TF_RND(6)  x0 += ks0; x1 += ks1 + 3u;
    TF_RND(17) TF_RND(29) TF_RND(16) TF_RND(24) x0 += ks1; x1 += ks2 + 4u;
    TF_RND(13) TF_RND(15) TF_RND(26) TF_RND(6)  x0 += ks2; x1 += ks0 + 5u;
#undef TF_RND
    return make_uint2(x0, x1);
}

__device__ __forceinline__ float my_tanh(float xv) {
    float ax = fabsf(xv);
    float t = __expf(-2.0f * ax);
    float r = (1.0f - t) / (1.0f + t);
    return copysignf(r, xv);
}
__device__ __forceinline__ float my_sig(float xv) {
    return 1.0f / (1.0f + __expf(-xv));
}

// 128-row matvec from SMEM: 8 warps x 16 rows
__device__ __forceinline__ void mv128(const float* W, const float* hv, float* dst, int tid) {
    const int lane = tid & 31, wrp = tid >> 5;
    const float4* HV = (const float4*)hv;
    float4 ha = HV[lane], hb = HV[lane + 32];
#pragma unroll 4
    for (int rr = 0; rr < 16; rr++) {
        int r = wrp * 16 + rr;
        const float4* wh = (const float4*)(W + r * LSTMN);
        float4 a = wh[lane], b4 = wh[lane + 32];
        float acc = a.x * ha.x + a.y * ha.y + a.z * ha.z + a.w * ha.w
                  + b4.x * hb.x + b4.y * hb.y + b4.z * hb.z + b4.w * hb.w;
        acc += __shfl_xor_sync(0xffffffffu, acc, 16);
        acc += __shfl_xor_sync(0xffffffffu, acc, 8);
        acc += __shfl_xor_sync(0xffffffffu, acc, 4);
        acc += __shfl_xor_sync(0xffffffffu, acc, 2);
        acc += __shfl_xor_sync(0xffffffffu, acc, 1);
        if (lane == 0) dst[r] = acc;
    }
}

// gx for own 128 gate rows, reading w_ih straight from GLOBAL (L2-resident)
__device__ __forceinline__ void gx_global(const float* __restrict__ Wg, const float* hv,
                                          float* dst, int tid, int rank) {
    const int lane = tid & 31, wrp = tid >> 5;
    const float4* HV = (const float4*)hv;
    float4 ha = HV[lane], hb = HV[lane + 32];
#pragma unroll 4
    for (int rr = 0; rr < 16; rr++) {
        int r = wrp * 16 + rr;
        int grow = ((r >> 5) << 8) + rank * EPC + (r & 31);
        const float4* wi = (const float4*)(Wg + (size_t)grow * LSTMN);
        float4 a = wi[lane], b4 = wi[lane + 32];
        float acc = a.x * ha.x + a.y * ha.y + a.z * ha.z + a.w * ha.w
                  + b4.x * hb.x + b4.y * hb.y + b4.z * hb.z + b4.w * hb.w;
        acc += __shfl_xor_sync(0xffffffffu, acc, 16);
        acc += __shfl_xor_sync(0xffffffffu, acc, 8);
        acc += __shfl_xor_sync(0xffffffffu, acc, 4);
        acc += __shfl_xor_sync(0xffffffffu, acc, 2);
        acc += __shfl_xor_sync(0xffffffffu, acc, 1);
        if (lane == 0) dst[r] = acc;
    }
}

// 32-row matvec (all 256 threads, 8 lanes/row)
__device__ __forceinline__ void mv32(const float* W, const float* hv, float* dst, int tid) {
    int row = tid >> 3, l8 = tid & 7;
    const float4* wr = (const float4*)(W + row * LSTMN) + l8 * 8;
    const float4* hp = ((const float4*)hv) + l8 * 8;
    float acc = 0.0f;
#pragma unroll
    for (int kk = 0; kk < 8; kk++) {
        float4 w4 = wr[kk], h4 = hp[kk];
        acc += w4.x * h4.x + w4.y * h4.y + w4.z * h4.z + w4.w * h4.w;
    }
    acc += __shfl_xor_sync(0xffffffffu, acc, 4);
    acc += __shfl_xor_sync(0xffffffffu, acc, 2);
    acc += __shfl_xor_sync(0xffffffffu, acc, 1);
    if (l8 == 0) dst[row] = acc;
}

// single-candidate H phase (tid<EPC): gate stride = 32; push plane kpar slot 0
__device__ __forceinline__ void h_single(Smem* s, int rank, int tid, int xs, int kpar, bool hzero) {
    if (tid < EPC) {
        int j = tid;
        float gi = (hzero ? 0.0f : s->gtmp[j])       + s->gxc[xs][j]       + s->bsum[j];
        float gf = (hzero ? 0.0f : s->gtmp[32 + j])  + s->gxc[xs][32 + j]  + s->bsum[32 + j];
        float gg = (hzero ? 0.0f : s->gtmp[64 + j])  + s->gxc[xs][64 + j]  + s->bsum[64 + j];
        float go = (hzero ? 0.0f : s->gtmp[96 + j])  + s->gxc[xs][96 + j]  + s->bsum[96 + j];
        float cn = my_sig(gf) * s->c32[j] + my_sig(gi) * my_tanh(gg);
        float hn = my_sig(go) * my_tanh(cn);
        s->c32[j] = cn;
        uint32_t ha = sm_u32(&s->candh[kpar][0][rank * EPC + j]);
#pragma unroll
        for (int r = 0; r < CLSZ; r++) ds_st(ha, (uint32_t)r, hn);
    }
}

// ---------------- main kernel: one 8-CTA cluster per block ----------------
__global__ void __launch_bounds__(NTH, 1) ctrl_kernel(
    const float* __restrict__ enc_w, const float* __restrict__ w_ih,
    const float* __restrict__ w_hh, const float* __restrict__ b_ih,
    const float* __restrict__ b_hh, const float* __restrict__ w1,
    const float* __restrict__ w2, const float* __restrict__ v,
    float* __restrict__ out)
{
    extern __shared__ char smraw[];
    Smem* s = (Smem*)smraw;
    const int tid = threadIdx.x;
    const int rank = (int)ctarank();
    const int b = blockIdx.y;

    // ---- prologue ----
    {
        // whh rows: local lr -> global (lr/32)*256 + rank*32 + lr%32
        for (int i = tid; i < GR * 64; i += NTH) {
            int lr = i >> 6, pos = i & 63;
            int grow = ((lr >> 5) << 8) + rank * EPC + (lr & 31);
            ((float4*)s->whh)[i] = ((const float4*)w_hh)[grow * 64 + pos];
        }
        for (int i = tid; i < EPC * 64; i += NTH) {
            int row = i >> 6, pos = i & 63;
            ((float4*)s->w1r)[i] = ((const float4*)w1)[(rank * EPC + row) * 64 + pos];
            ((float4*)s->w2r)[i] = ((const float4*)w2)[(rank * EPC + row) * 64 + pos];
        }
        if (tid < GR) {
            int grow = ((tid >> 5) << 8) + rank * EPC + (tid & 31);
            s->bsum[tid] = b_ih[grow] + b_hh[grow];
#pragma unroll
            for (int xs = 1; xs < 6; xs++) s->gxc[xs][tid] = 0.0f;
        }
        if (tid < EPC) { s->v32[tid] = v[rank * EPC + tid]; s->c32[tid] = 0.0f; }
        s->hanc[tid] = enc_w[tid];   // enc0 staging
        if (tid == 0) {
            s->lp = 0.0f; s->ent = 0.0f; s->idx = 0;
            uint32_t ma = sm_u32(&s->mbar);
            asm volatile("mbarrier.init.shared.b64 [%0], %1;" :: "r"(ma), "r"(CLSZ) : "memory");
        }
    }
    __syncthreads();
    gx_global(w_ih, s->hanc, s->gxc[0], tid, rank);   // gx(enc0)
    asm volatile("barrier.cluster.arrive.aligned;" ::: "memory");
    asm volatile("barrier.cluster.wait.aligned;" ::: "memory");

    const uint2 key42 = make_uint2(0u, 42u);
    const uint2 bkey = tf2x32(key42, make_uint2(0u, (uint32_t)b));

    int k = 0;
    // ---- k0: Z cell (zero state, input enc0) ----
    __syncthreads();
    h_single(s, rank, tid, 0, 0, true);
    round_arrive(s, tid);
    round_wait(s, k); k++;
    const float* hcur = s->candh[0][0];
    __syncthreads();

    // ---- k1: aw1[0]=aw1[1]; priming cell(enc0, h1) ----
    mv128(s->whh, hcur, s->gtmp, tid);
    mv32(s->w1r, hcur, s->aw1l[0], tid);
    __syncthreads();
    if (tid < EPC) s->aw1l[1][tid] = s->aw1l[0][tid];
    h_single(s, rank, tid, 0, 1, false);
    round_arrive(s, tid);
    round_wait(s, k); k++;
    hcur = s->candh[1][0];
    __syncthreads();

    int step = 0;
#pragma unroll 1
    for (int layer = 2; layer <= 6; layer++) {
        const int ncand = layer - 1;   // live candidates: xs in {1..layer-1}
#pragma unroll 1
        for (int rep = 0; rep < 2; rep++) {
            const int kpar = k & 1;
            const bool pushc = !(layer == 6 && rep == 1);
            // pre-round: recurrent gates + w2h (both all-256-thread)
            mv128(s->whh, hcur, s->gtmp, tid);
            mv32(s->w2r, hcur, s->w2h32, tid);
            __syncthreads();
            // phase1: candidates (threads 96..255) | gumbel (threads 0..7)
            if (tid >= 96) {
                int c = (tid - 96) >> 5, j = (tid - 96) & 31;
                if (c < ncand) {
                    int xs = c + 1;
                    float gi = s->gtmp[j]      + s->gxc[xs][j]      + s->bsum[j];
                    float gf = s->gtmp[32 + j] + s->gxc[xs][32 + j] + s->bsum[32 + j];
                    float gg = s->gtmp[64 + j] + s->gxc[xs][64 + j] + s->bsum[64 + j];
                    float go = s->gtmp[96 + j] + s->gxc[xs][96 + j] + s->bsum[96 + j];
                    float cn = my_sig(gf) * s->c32[j] + my_sig(gi) * my_tanh(gg);
                    float hn = my_sig(go) * my_tanh(cn);
                    s->candc[c][j] = cn;
                    if (pushc) {
                        uint32_t ha = sm_u32(&s->candh[kpar][c][rank * EPC + j]);
#pragma unroll
                        for (int r = 0; r < CLSZ; r++) ds_st(ha, (uint32_t)r, hn);
                    } else {
                        s->candh[kpar][c][rank * EPC + j] = hn;   // local (final cell)
                    }
                }
            } else if (tid < 8) {
                if (tid < layer) {
                    uint2 skey = tf2x32(bkey, make_uint2(0u, (uint32_t)step));
                    uint2 o = tf2x32(skey, make_uint2(0u, (uint32_t)tid));
                    uint32_t bits = o.x ^ o.y;
                    float u = __uint_as_float((bits >> 9) | 0x3f800000u) - 1.0f;
                    const float TINYF = 1.17549435e-38f;
                    float up = fmaxf(TINYF, u + TINYF);
                    s->gum[tid] = -logf(-logf(up));   // accurate: index fidelity
                }
            }
            __syncthreads();
            // phase2: qv partials — warp l handles layer l over own 32 elems
            {
                int l = tid >> 5, j = tid & 31;
                if (l < layer) {
                    float val = my_tanh(s->aw1l[l][j] + s->w2h32[j]) * s->v32[j];
                    val += __shfl_xor_sync(0xffffffffu, val, 16);
                    val += __shfl_xor_sync(0xffffffffu, val, 8);
                    val += __shfl_xor_sync(0xffffffffu, val, 4);
                    val += __shfl_xor_sync(0xffffffffu, val, 2);
                    val += __shfl_xor_sync(0xffffffffu, val, 1);
                    if (j == 0) {
                        uint32_t ra = sm_u32(&s->red2[kpar][l * CLSZ + rank]);
#pragma unroll
                        for (int r = 0; r < CLSZ; r++) ds_st(ra, (uint32_t)r, val);
                    }
                }
            }
            round_arrive(s, tid);
            round_wait(s, k); k++;

            // post-round: logits + Gumbel argmax (warp 0, replicated)
            if (tid < 32) {
                const int lane = tid;
                const bool act = lane < layer;
                float logit = 0.0f;
                if (act) {
                    float sum = 0.0f;
#pragma unroll
                    for (int r = 0; r < CLSZ; r++) sum += s->red2[kpar][lane * CLSZ + r];
                    logit = 1.1f * my_tanh(sum * 0.2f);
                }
                float pert = act ? (s->gum[lane] + logit) : -1e38f;
                float bp = pert; int bi = act ? lane : 64;
#pragma unroll
                for (int off = 16; off; off >>= 1) {
                    float op = __shfl_xor_sync(0xffffffffu, bp, off);
                    int oi = __shfl_xor_sync(0xffffffffu, bi, off);
                    if (op > bp || (op == bp && oi < bi)) { bp = op; bi = oi; }
                }
                float lm = act ? logit : -1e38f;
#pragma unroll
                for (int off = 16; off; off >>= 1)
                    lm = fmaxf(lm, __shfl_xor_sync(0xffffffffu, lm, off));
                float se = act ? __expf(logit - lm) : 0.0f;
#pragma unroll
                for (int off = 16; off; off >>= 1)
                    se += __shfl_xor_sync(0xffffffffu, se, off);
                float lse = __logf(se);
                float ls = logit - lm - lse;
                float ls_best = __shfl_sync(0xffffffffu, ls, bi);
                float ec = act ? (-ls * __expf(ls)) : 0.0f;
#pragma unroll
                for (int off = 16; off; off >>= 1)
                    ec += __shfl_xor_sync(0xffffffffu, ec, off);
                if (lane == 0) {
                    s->lp += -ls_best;
                    s->ent += ec;
                    s->idx = bi;
                    if (rank == 0) out[b * 10 + step] = (float)bi;
                }
            }
            __syncthreads();
            int sel = ((s->idx < 2) ? 1 : s->idx) - 1;
            if (tid < EPC) s->c32[tid] = s->candc[sel][tid];
            hcur = s->candh[kpar][sel];
            step++;
            __syncthreads();
        }
        if (layer < 6) {
            const int kpar = k & 1;
            // anchor round: hcur = anchor h (selected candidate)
            s->hanc[tid] = hcur[tid];             // private copy (pre-arrive read)
            __syncthreads();
            mv128(s->whh, s->hanc, s->gtmp, tid); // recurrent part of cell(enc0, anchor)
            __syncthreads();
            h_single(s, rank, tid, 0, kpar, false);
            round_arrive(s, tid);
            // overlap with barrier wait: anchor bookkeeping
            mv32(s->w1r, s->hanc, s->aw1l[layer], tid);
            gx_global(w_ih, s->hanc, s->gxc[layer], tid, rank);
            round_wait(s, k); k++;
            hcur = s->candh[kpar][0];
            __syncthreads();
        }
    }

    // ---- epilogue: deadlock-free last-cluster scalar reduction ----
    if (rank == 0 && tid == 0) {
        g_lp[b] = s->lp;
        g_ent[b] = s->ent;
        __threadfence();
        int prev = atomicAdd(&g_count, 1);
        if (prev == NBLK - 1) {
            __threadfence();
            float slp = 0.0f, sent = 0.0f;
#pragma unroll
            for (int bb = 0; bb < NBLK; bb++) {
                slp += ((volatile float*)g_lp)[bb];
                sent += ((volatile float*)g_ent)[bb];
            }
            out[60] = slp;
            out[61] = sent;
            g_count = 0;   // reset for graph replay
        }
    }
    __syncthreads();
    if (b == NBLK - 1 && tid < EPC) {
        out[62 + rank * EPC + tid] = s->c32[tid];                 // final c (own slice)
        out[62 + 256 + rank * EPC + tid] = hcur[rank * EPC + tid]; // final h (own slice)
    }
}

extern "C" void kernel_launch(void* const* d_in, const int* in_sizes, int n_in,
                              void* d_out, int out_size) {
    const float* enc_w = (const float*)d_in[0];
    const float* w_ih  = (const float*)d_in[1];
    const float* w_hh  = (const float*)d_in[2];
    const float* b_ih  = (const float*)d_in[3];
    const float* b_hh  = (const float*)d_in[4];
    const float* w1    = (const float*)d_in[5];
    const float* w2    = (const float*)d_in[6];
    const float* v     = (const float*)d_in[7];
    float* out = (float*)d_out;

    cudaFuncSetAttribute(ctrl_kernel,
                         cudaFuncAttributeMaxDynamicSharedMemorySize,
                         (int)sizeof(Smem));
    cudaFuncSetAttribute(ctrl_kernel,
                         cudaFuncAttributeNonPortableClusterSizeAllowed, 1);

    cudaLaunchConfig_t cfg = {};
    cfg.gridDim = dim3(CLSZ, NBLK, 1);
    cfg.blockDim = dim3(NTH, 1, 1);
    cfg.dynamicSmemBytes = sizeof(Smem);
    cfg.stream = 0;
    cudaLaunchAttribute at[1];
    at[0].id = cudaLaunchAttributeClusterDimension;
    at[0].val.clusterDim.x = CLSZ;
    at[0].val.clusterDim.y = 1;
    at[0].val.clusterDim.z = 1;
    cfg.attrs = at;
    cfg.numAttrs = 1;

    cudaLaunchKernelEx(&cfg, ctrl_kernel,
                       enc_w, w_ih, w_hh, b_ih, b_hh, w1, w2, v, out);
}

// round 16
// speedup vs baseline: 1.5230x; 1.5230x over previous
#include <cuda_runtime.h>
#include <cstdint>
#include <math.h>

#define LSTMN 256
#define CLSZ  16
#define NTH   256
#define NBLK  6

struct __align__(16) Smem {
    float wih[64 * 256];   // 64 KB: own gate rows (gate q, elems [16r,16r+16))
    float whh[64 * 256];   // 64 KB
    float w1c[256 * 16];   // 16 KB: w1 columns [rank*16, rank*16+16)
    float w2c[256 * 16];   // 16 KB: w2 columns
    float h[2][256];       // double-buffered replicated h
    float v[256];
    float gxc[6][64];      // gx cache: 0=enc0, 1=zero(anchors 0/1), 2..5=anchors
    float g[64], bsum[64];
    float hseg[16], c16[16];
    float pw1[256];        // column partial of w1 @ h
    float pw2[256];        // column partial of w2 @ h
    float my_aw1[128];     // (layer,half) CTA's gathered anchors_w1 slice
    float red[16];         // [0..11] logit partials (2/layer); [12..15] scratch
    float gum[8];
    float lp, ent;
    int   idx;
};

__device__ float g_lp[NBLK];
__device__ float g_ent[NBLK];
__device__ int   g_count;

// ---------------- low-level helpers ----------------

__device__ __forceinline__ uint32_t sm_u32(const void* p) {
    return (uint32_t)__cvta_generic_to_shared(p);
}
__device__ __forceinline__ uint32_t ctarank() {
    uint32_t r; asm("mov.u32 %0, %%cluster_ctarank;" : "=r"(r)); return r;
}
__device__ __forceinline__ float ds_ld(uint32_t laddr, uint32_t rank) {
    uint32_t ra; float val;
    asm volatile("mapa.shared::cluster.u32 %0, %1, %2;" : "=r"(ra) : "r"(laddr), "r"(rank));
    asm volatile("ld.shared::cluster.f32 %0, [%1];" : "=f"(val) : "r"(ra));
    return val;
}
__device__ __forceinline__ void ds_st(uint32_t laddr, uint32_t rank, float val) {
    uint32_t ra;
    asm volatile("mapa.shared::cluster.u32 %0, %1, %2;" : "=r"(ra) : "r"(laddr), "r"(rank));
    asm volatile("st.shared::cluster.f32 [%0], %1;" :: "r"(ra), "f"(val) : "memory");
}
__device__ __forceinline__ void csync() {
    asm volatile("barrier.cluster.arrive.aligned;" ::: "memory");
    asm volatile("barrier.cluster.wait.aligned;" ::: "memory");
}

// threefry2x32, 20 rounds — exact JAX semantics
__device__ __forceinline__ uint2 tf2x32(uint2 key, uint2 ctr) {
    uint32_t ks0 = key.x, ks1 = key.y, ks2 = ks0 ^ ks1 ^ 0x1BD11BDAu;
    uint32_t x0 = ctr.x + ks0, x1 = ctr.y + ks1;
#define TF_RND(r) { x0 += x1; x1 = (x1 << (r)) | (x1 >> (32 - (r))); x1 ^= x0; }
    TF_RND(13) TF_RND(15) TF_RND(26) TF_RND(6)  x0 += ks1; x1 += ks2 + 1u;
    TF_RND(17) TF_RND(29) TF_RND(16) TF_RND(24) x0 += ks2; x1 += ks0 + 2u;
    TF_RND(13) TF_RND(15) TF_RND(26) TF_RND(6)  x0 += ks0; x1 += ks1 + 3u;
    TF_RND(17) TF_RND(29) TF_RND(16) TF_RND(24) x0 += ks1; x1 += ks2 + 4u;
    TF_RND(13) TF_RND(15) TF_RND(26) TF_RND(6)  x0 += ks2; x1 += ks0 + 5u;
#undef TF_RND
    return make_uint2(x0, x1);
}

// fast MUFU-path tanh/sigmoid (R10/R12-proven; err ~1e-6 vs 1e-3 tolerance)
__device__ __forceinline__ float my_tanh(float xv) {
    float ax = fabsf(xv);
    float t = __expf(-2.0f * ax);
    float r = (1.0f - t) / (1.0f + t);
    return copysignf(r, xv);
}
__device__ __forceinline__ float my_sig(float xv) {
    return 1.0f / (1.0f + __expf(-xv));
}

// 64-row matvec: dst[r] = W[r,:] @ hv  (8 warps x 8 rows)
__device__ __forceinline__ void mv64(const float* W, const float* hv, float* dst, int tid) {
    const int lane = tid & 31, wrp = tid >> 5;
    const float4* HV = (const float4*)hv;
    float4 ha = HV[lane], hb = HV[lane + 32];
#pragma unroll
    for (int rr = 0; rr < 8; rr++) {
        int r = wrp * 8 + rr;
        const float4* wh = (const float4*)(W + r * LSTMN);
        float4 a = wh[lane], b4 = wh[lane + 32];
        float acc = a.x * ha.x + a.y * ha.y + a.z * ha.z + a.w * ha.w
                  + b4.x * hb.x + b4.y * hb.y + b4.z * hb.z + b4.w * hb.w;
        acc += __shfl_xor_sync(0xffffffffu, acc, 16);
        acc += __shfl_xor_sync(0xffffffffu, acc, 8);
        acc += __shfl_xor_sync(0xffffffffu, acc, 4);
        acc += __shfl_xor_sync(0xffffffffu, acc, 2);
        acc += __shfl_xor_sync(0xffffffffu, acc, 1);
        if (lane == 0) dst[r] = acc;
    }
}

// ---------------- one LSTM cell (R6 skeleton + gxc + double-buffered h) ----------
// mode 0: sample cell (pw2) | 1: anchor cell (pw1) | 2: final (local only)
// hzero: h == 0 (Z cell) — skip recurrent matvec entirely
__device__ __forceinline__ void do_cell(Smem* s, int rank, int tid, int mode,
                                        int xs, bool hzero, int hb) {
    __syncthreads();
    if (hzero) {
        if (tid < 64) s->g[tid] = s->gxc[xs][tid] + s->bsum[tid];
    } else {
        const int lane = tid & 31, wrp = tid >> 5;
        const float4* HV = (const float4*)s->h[hb];
        float4 ha = HV[lane], hbv = HV[lane + 32];
#pragma unroll
        for (int rr = 0; rr < 8; rr++) {
            int r = wrp * 8 + rr;
            const float4* wh = (const float4*)(s->whh + r * LSTMN);
            float4 a = wh[lane], b4 = wh[lane + 32];
            float acc = a.x * ha.x + a.y * ha.y + a.z * ha.z + a.w * ha.w
                      + b4.x * hbv.x + b4.y * hbv.y + b4.z * hbv.z + b4.w * hbv.w;
            acc += __shfl_xor_sync(0xffffffffu, acc, 16);
            acc += __shfl_xor_sync(0xffffffffu, acc, 8);
            acc += __shfl_xor_sync(0xffffffffu, acc, 4);
            acc += __shfl_xor_sync(0xffffffffu, acc, 2);
            acc += __shfl_xor_sync(0xffffffffu, acc, 1);
            if (lane == 0) s->g[r] = acc + s->gxc[xs][r] + s->bsum[r];
        }
    }
    __syncthreads();

    // H phase: local (own 16 elements); push new h into buffer hb^1
    if (tid < 16) {
        int j = tid;
        float gi = s->g[j], gf = s->g[16 + j], gg = s->g[32 + j], go = s->g[48 + j];
        float cn = my_sig(gf) * s->c16[j] + my_sig(gi) * my_tanh(gg);
        float hn = my_sig(go) * my_tanh(cn);
        s->c16[j] = cn;
        s->hseg[j] = hn;
        if (mode != 2) {
            uint32_t ha = sm_u32(&s->h[hb ^ 1][rank * 16 + j]);
#pragma unroll
            for (int r = 0; r < CLSZ; r++) ds_st(ha, (uint32_t)r, hn);
        }
    }
    __syncthreads();

    if (mode != 2) {
        // local column-partial matvec over own h segment (R6 verbatim)
        const float* wc = (mode == 1 ? s->w1c : s->w2c) + tid * 16;
        float acc = 0.0f;
#pragma unroll
        for (int k = 0; k < 16; k++) acc = fmaf(wc[k], s->hseg[k], acc);
        if (mode == 1) s->pw1[tid] = acc; else s->pw2[tid] = acc;
        csync();   // h broadcast + partials visible cluster-wide
    }
}

// gather summed anchors_w1 slice for (layer l, half) CTAs serving slot — R6 verbatim
__device__ __forceinline__ void do_anchor_gather(Smem* s, int rank, int tid, int slot) {
    int half = rank >> 3, l = rank & 7;
    bool gat = (l == slot) || (slot == 0 && l == 1);
    if (gat && tid < 128) {
        uint32_t pa = sm_u32(&s->pw1[half * 128 + tid]);
        float a = 0.0f;
#pragma unroll
        for (int r = 0; r < CLSZ; r++) a += ds_ld(pa, (uint32_t)r);
        s->my_aw1[tid] = a;
    }
}

// ---------------- sampling (R6 machinery + warp-7 Gumbel + fastmath) ------------
__device__ __forceinline__ void do_sample(Smem* s, int rank, int tid, int layer,
                                          uint2 bkey, int step, float* out, int b) {
    const int lane = tid & 31, wrp = tid >> 5;
    const int half = rank >> 3, l = rank & 7;

    // qv: CTA (l,half) pulls pw2 and computes its half of layer-l's logit
    if (l < layer && tid < 128) {
        uint32_t pa = sm_u32(&s->pw2[half * 128 + tid]);
        float a = 0.0f;
#pragma unroll
        for (int r = 0; r < CLSZ; r++) a += ds_ld(pa, (uint32_t)r);
        int e = half * 128 + tid;
        float val = my_tanh(s->my_aw1[tid] + a) * s->v[e];
        val += __shfl_xor_sync(0xffffffffu, val, 16);
        val += __shfl_xor_sync(0xffffffffu, val, 8);
        val += __shfl_xor_sync(0xffffffffu, val, 4);
        val += __shfl_xor_sync(0xffffffffu, val, 2);
        val += __shfl_xor_sync(0xffffffffu, val, 1);
        if (lane == 0) s->red[12 + wrp] = val;
    } else if (tid >= 224) {
        // warp 7 (idle in qv): Gumbel precompute — accurate logf (index fidelity)
        int gl = tid - 224;
        if (gl < layer) {
            uint2 skey = tf2x32(bkey, make_uint2(0u, (uint32_t)step));
            uint2 o = tf2x32(skey, make_uint2(0u, (uint32_t)gl));
            uint32_t bits = o.x ^ o.y;
            float u = __uint_as_float((bits >> 9) | 0x3f800000u) - 1.0f;
            const float TINYF = 1.17549435e-38f;
            float up = fmaxf(TINYF, u + TINYF);
            s->gum[gl] = -logf(-logf(up));
        }
    }
    __syncthreads();
    if (l < layer && tid == 0) {
        float p = s->red[12] + s->red[13] + s->red[14] + s->red[15];
        uint32_t ra = sm_u32(&s->red[2 * l + half]);
#pragma unroll
        for (int r = 0; r < CLSZ; r++) ds_st(ra, (uint32_t)r, p);
    }
    csync();   // partial logits visible everywhere

    // warp 0: logits + Gumbel argmax (replicated per CTA)
    if (tid < 32) {
        const bool act = lane < layer;
        float logit = 0.0f;
        if (act)
            logit = 1.1f * my_tanh((s->red[2 * lane] + s->red[2 * lane + 1]) * 0.2f);
        float pert = act ? (s->gum[lane] + logit) : -1e38f;
        float bp = pert; int bi = act ? lane : 64;
#pragma unroll
        for (int off = 16; off; off >>= 1) {
            float op = __shfl_xor_sync(0xffffffffu, bp, off);
            int oi = __shfl_xor_sync(0xffffffffu, bi, off);
            if (op > bp || (op == bp && oi < bi)) { bp = op; bi = oi; }
        }
        float lm = act ? logit : -1e38f;
#pragma unroll
        for (int off = 16; off; off >>= 1)
            lm = fmaxf(lm, __shfl_xor_sync(0xffffffffu, lm, off));
        float se = act ? __expf(logit - lm) : 0.0f;
#pragma unroll
        for (int off = 16; off; off >>= 1)
            se += __shfl_xor_sync(0xffffffffu, se, off);
        float lse = __logf(se);
        float ls = logit - lm - lse;
        float ls_best = __shfl_sync(0xffffffffu, ls, bi);
        float ec = act ? (-ls * __expf(ls)) : 0.0f;
#pragma unroll
        for (int off = 16; off; off >>= 1)
            ec += __shfl_xor_sync(0xffffffffu, ec, off);
        if (lane == 0) {
            s->lp += -ls_best;
            s->ent += ec;
            s->idx = bi;
            if (rank == 0) out[b * 10 + step] = (float)bi;
        }
    }
    __syncthreads();   // idx visible to all
}

// ---------------- main kernel: one 16-CTA cluster per block ----------------
__global__ void __launch_bounds__(NTH, 1) ctrl_kernel(
    const float* __restrict__ enc_w, const float* __restrict__ w_ih,
    const float* __restrict__ w_hh, const float* __restrict__ b_ih,
    const float* __restrict__ b_hh, const float* __restrict__ w1,
    const float* __restrict__ w2, const float* __restrict__ v,
    float* __restrict__ out)
{
    extern __shared__ char smraw[];
    Smem* s = (Smem*)smraw;
    const int tid = threadIdx.x;
    const int rank = (int)ctarank();
    const int b = blockIdx.y;

    // ---- prologue (R6 weight mapping verbatim) ----
    {
        for (int i = tid; i < 64 * 64; i += NTH) {
            int lr = i >> 6, pos = i & 63;
            int grow = ((lr >> 4) << 8) + rank * 16 + (lr & 15);
            ((float4*)s->wih)[i] = ((const float4*)w_ih)[grow * 64 + pos];
        }
        for (int i = tid; i < 64 * 64; i += NTH) {
            int lr = i >> 6, pos = i & 63;
            int grow = ((lr >> 4) << 8) + rank * 16 + (lr & 15);
            ((float4*)s->whh)[i] = ((const float4*)w_hh)[grow * 64 + pos];
        }
        {
            int j = tid;
            const float4* s1 = (const float4*)(w1 + j * 256 + rank * 16);
            const float4* s2 = (const float4*)(w2 + j * 256 + rank * 16);
            float4* d1 = (float4*)(s->w1c + j * 16);
            float4* d2 = (float4*)(s->w2c + j * 16);
#pragma unroll
            for (int k = 0; k < 4; k++) { d1[k] = s1[k]; d2[k] = s2[k]; }
        }
        if (tid < 64) {
            int grow = ((tid >> 4) << 8) + rank * 16 + (tid & 15);
            s->bsum[tid] = b_ih[grow] + b_hh[grow];
            s->gxc[1][tid] = 0.0f;   // anchors 0/1 are zero vectors
        }
        s->v[tid] = v[tid];
        s->h[0][tid] = enc_w[tid];   // temp: enc0 as matvec input
        if (tid < 16) s->c16[tid] = 0.0f;
        if (tid == 0) { s->lp = 0.0f; s->ent = 0.0f; s->idx = 0; }
    }
    __syncthreads();
    mv64(s->wih, s->h[0], s->gxc[0], tid);   // gxc[0] = wih @ enc0
    csync();   // enc0 reads done everywhere before Z-cell pushes overwrite h[0]

    const uint2 key42 = make_uint2(0u, 42u);
    const uint2 bkey = tf2x32(key42, make_uint2(0u, (uint32_t)b));

    // Z cell (zero state, input enc0): g = gxc[0] + bsum; pushes h1 -> h[0]
    int hb = 1;
    do_cell(s, rank, tid, 1, 0, true, hb);
    hb = 0;                              // h1 in h[0]
    do_anchor_gather(s, rank, tid, 0);   // aw1 slices for layers 0 & 1

    int step = 0;
#pragma unroll 1
    for (int layer = 2; layer <= 6; layer++) {
        // two sample cells: BOTH always followed by a sample (10 samples total)
#pragma unroll 1
        for (int rep = 0; rep < 2; rep++) {
            int xs = (rep == 0) ? 0 : ((s->idx < 2) ? 1 : s->idx);
            do_cell(s, rank, tid, 0, xs, false, hb);
            hb ^= 1;
            do_sample(s, rank, tid, layer, bkey, step, out, b);
            step++;
        }
        // layer-final anchor cell (input anchors[idx of sample 2])
        int xs = (s->idx < 2) ? 1 : s->idx;
        if (layer < 6) {
            do_cell(s, rank, tid, 1, xs, false, hb);
            hb ^= 1;
            do_anchor_gather(s, rank, tid, layer);
            mv64(s->wih, s->h[hb], s->gxc[layer], tid);  // gx cache of new anchor
            __syncthreads();
        } else {
            do_cell(s, rank, tid, 2, xs, false, hb);     // final: local c,h only
        }
    }

    // ---- epilogue: deadlock-free last-cluster scalar reduction ----
    if (rank == 0 && tid == 0) {
        g_lp[b] = s->lp;
        g_ent[b] = s->ent;
        __threadfence();
        int prev = atomicAdd(&g_count, 1);
        if (prev == NBLK - 1) {
            __threadfence();
            float slp = 0.0f, sent = 0.0f;
#pragma unroll
            for (int bb = 0; bb < NBLK; bb++) {
                slp += ((volatile float*)g_lp)[bb];
                sent += ((volatile float*)g_ent)[bb];
            }
            out[60] = slp;
            out[61] = sent;
            g_count = 0;   // reset for graph replay
        }
    }
    __syncthreads();
    if (b == NBLK - 1 && tid < 16) {
        out[62 + rank * 16 + tid] = s->c16[tid];
        out[62 + 256 + rank * 16 + tid] = s->hseg[tid];
    }
}

extern "C" void kernel_launch(void* const* d_in, const int* in_sizes, int n_in,
                              void* d_out, int out_size) {
    const float* enc_w = (const float*)d_in[0];
    const float* w_ih  = (const float*)d_in[1];
    const float* w_hh  = (const float*)d_in[2];
    const float* b_ih  = (const float*)d_in[3];
    const float* b_hh  = (const float*)d_in[4];
    const float* w1    = (const float*)d_in[5];
    const float* w2    = (const float*)d_in[6];
    const float* v     = (const float*)d_in[7];
    float* out = (float*)d_out;

    cudaFuncSetAttribute(ctrl_kernel,
                         cudaFuncAttributeMaxDynamicSharedMemorySize,
                         (int)sizeof(Smem));
    cudaFuncSetAttribute(ctrl_kernel,
                         cudaFuncAttributeNonPortableClusterSizeAllowed, 1);

    cudaLaunchConfig_t cfg = {};
    cfg.gridDim = dim3(CLSZ, NBLK, 1);
    cfg.blockDim = dim3(NTH, 1, 1);
    cfg.dynamicSmemBytes = sizeof(Smem);
    cfg.stream = 0;
    cudaLaunchAttribute at[1];
    at[0].id = cudaLaunchAttributeClusterDimension;
    at[0].val.clusterDim.x = CLSZ;
    at[0].val.clusterDim.y = 1;
    at[0].val.clusterDim.z = 1;
    cfg.attrs = at;
    cfg.numAttrs = 1;

    cudaLaunchKernelEx(&cfg, ctrl_kernel,
                       enc_w, w_ih, w_hh, b_ih, b_hh, w1, w2, v, out);
}